// round 9
// baseline (speedup 1.0000x reference)
#include <cuda_runtime.h>
#include <cstdint>

// AccumulateLoss: P=10 pose pairs, B batch. 10 triples (i<k<j) over CONTINLEN=5.
// loss = 50 * sum||R1@R2 - R12||^2 + sum||R1@t1 + t2 - t12||^2
// DRAM-bound (126MB, floor ~16-18us). R8: single-kernel graph (last-block
// reduction, no init kernel) + 3-deep cp.async.bulk ring so every block keeps
// ~2 fills outstanding and the per-tile wakeup/LDS/sync segment is off the
// DRAM stream's critical path.

#define NPAIRS 10
#define TILE   64                         // batch elems per tile (= threads/block)
#define BPB    64
#define RFLOATS (NPAIRS * TILE * 9)       // 5760 floats per buffer (rot)
#define TFLOATS (NPAIRS * TILE * 3)       // 1920 floats per buffer (trans)
#define BUF_FLOATS (RFLOATS + TFLOATS)    // 7680
#define BUF_BYTES  (BUF_FLOATS * 4)       // 30720
#define NSTAGES 3
#define NBLOCKS 304                       // 2 per SM on 152-SM GB300
#define MAXGRID 512

__device__ float        hx_partial[MAXGRID];
__device__ unsigned int hx_count;         // zero-init .bss; self-resetting

__device__ __forceinline__ uint32_t smem_u32(const void* p) {
    return (uint32_t)__cvta_generic_to_shared(p);
}
__device__ __forceinline__ void mbar_init(uint32_t a, uint32_t cnt) {
    asm volatile("mbarrier.init.shared.b64 [%0], %1;" :: "r"(a), "r"(cnt) : "memory");
}
__device__ __forceinline__ void mbar_expect_tx(uint32_t a, uint32_t bytes) {
    asm volatile("mbarrier.arrive.expect_tx.shared.b64 _, [%0], %1;"
                 :: "r"(a), "r"(bytes) : "memory");
}
__device__ __forceinline__ void mbar_wait(uint32_t a, uint32_t parity) {
    asm volatile(
        "{\n\t.reg .pred P;\n\t"
        "WAIT_LOOP_%=:\n\t"
        "mbarrier.try_wait.parity.acquire.cta.shared::cta.b64 P, [%0], %1, 0x989680;\n\t"
        "@P bra.uni WAIT_DONE_%=;\n\t"
        "bra.uni WAIT_LOOP_%=;\n\t"
        "WAIT_DONE_%=:\n\t}"
        :: "r"(a), "r"(parity) : "memory");
}
__device__ __forceinline__ void bulk_g2s(uint32_t dst, const void* src,
                                         uint32_t bytes, uint32_t mbar) {
    asm volatile(
        "cp.async.bulk.shared::cluster.global.mbarrier::complete_tx::bytes "
        "[%0], [%1], %2, [%3];"
        :: "r"(dst), "l"(src), "r"(bytes), "r"(mbar) : "memory");
}

// Issue the 20 bulk copies for one tile into buffer `base` (one thread).
__device__ __forceinline__ void prefetch_tile(const float* __restrict__ rotas,
                                              const float* __restrict__ transs,
                                              int B, int tile,
                                              float* base, uint32_t mb) {
    mbar_expect_tx(mb, BUF_BYTES);
#pragma unroll
    for (int p = 0; p < NPAIRS; p++) {
        bulk_g2s(smem_u32(base + p * (TILE * 9)),
                 rotas + ((size_t)p * B + (size_t)tile * TILE) * 9,
                 TILE * 9 * 4, mb);
        bulk_g2s(smem_u32(base + RFLOATS + p * (TILE * 3)),
                 transs + ((size_t)p * B + (size_t)tile * TILE) * 3,
                 TILE * 3 * 4, mb);
    }
}

extern __shared__ float sbuf[];   // NSTAGES * BUF_FLOATS floats (92160 bytes)

__global__ void __launch_bounds__(BPB)
hx_accum_loss(const float* __restrict__ rotas,
              const float* __restrict__ transs,
              float* __restrict__ out, int B)
{
    __shared__ __align__(8) unsigned long long mbar[NSTAGES];
    __shared__ float red[2][2];
    __shared__ bool  amLast;

    const int tid = threadIdx.x;
    const int ntiles = B / TILE;
    const int stride = gridDim.x;
    const int t0 = blockIdx.x;

    if (tid == 0) {
#pragma unroll
        for (int s = 0; s < NSTAGES; s++) mbar_init(smem_u32(&mbar[s]), 1);
        asm volatile("fence.proxy.async.shared::cta;" ::: "memory");
    }
    __syncthreads();

    // Prologue: prefetch first NSTAGES tiles for this block.
    if (tid == 0) {
#pragma unroll
        for (int s = 0; s < NSTAGES; s++) {
            int t = t0 + s * stride;
            if (t < ntiles)
                prefetch_tile(rotas, transs, B, t,
                              sbuf + s * BUF_FLOATS, smem_u32(&mbar[s]));
        }
    }

    float rsa[4] = {0.f, 0.f, 0.f, 0.f};
    float tsa[2] = {0.f, 0.f};

    int phase[NSTAGES] = {0, 0, 0};
    int m = 0;
    for (int tile = t0; tile < ntiles; tile += stride, m++) {
        const int buf = m % NSTAGES;
        float* base = sbuf + buf * BUF_FLOATS;

        mbar_wait(smem_u32(&mbar[buf]), phase[buf]);
        phase[buf] ^= 1;

        // Pull my 120 floats smem -> regs (stride-9 / stride-3 LDS, conflict-free).
        float R[NPAIRS][9];
        float T[NPAIRS][3];
#pragma unroll
        for (int p = 0; p < NPAIRS; p++) {
            const float* rp = base + p * (TILE * 9) + tid * 9;
#pragma unroll
            for (int e = 0; e < 9; e++) R[p][e] = rp[e];
            const float* tp = base + RFLOATS + p * (TILE * 3) + tid * 3;
#pragma unroll
            for (int e = 0; e < 3; e++) T[p][e] = tp[e];
        }
        __syncthreads();   // everyone done reading this buffer

        // Refill this buffer with tile m+NSTAGES while we compute tile m.
        const int nxt = tile + NSTAGES * stride;
        if (tid == 0 && nxt < ntiles)
            prefetch_tile(rotas, transs, B, nxt, base, smem_u32(&mbar[buf]));

        // ---- compute: all indices compile-time; split accumulators break chains ----
#define TRIPLE(P1, P2, P12)                                                    \
        {                                                                      \
            _Pragma("unroll")                                                  \
            for (int i = 0; i < 3; i++) {                                      \
                _Pragma("unroll")                                              \
                for (int j = 0; j < 3; j++) {                                  \
                    float f = R[P1][i*3+0] * R[P2][0*3+j]                      \
                            + R[P1][i*3+1] * R[P2][1*3+j]                      \
                            + R[P1][i*3+2] * R[P2][2*3+j];                     \
                    float d = f - R[P12][i*3+j];                               \
                    rsa[(i*3+j) & 3] += d * d;                                 \
                }                                                              \
                float g = R[P1][i*3+0] * T[P1][0]                              \
                        + R[P1][i*3+1] * T[P1][1]                              \
                        + R[P1][i*3+2] * T[P1][2] + T[P2][i];                  \
                float dg = g - T[P12][i];                                      \
                tsa[i & 1] += dg * dg;                                         \
            }                                                                  \
        }

        TRIPLE(0, 4, 1)
        TRIPLE(0, 5, 2)
        TRIPLE(1, 7, 2)
        TRIPLE(0, 6, 3)
        TRIPLE(1, 8, 3)
        TRIPLE(2, 9, 3)
        TRIPLE(4, 7, 5)
        TRIPLE(4, 8, 6)
        TRIPLE(5, 9, 6)
        TRIPLE(7, 9, 8)
#undef TRIPLE
    }

    // ---- block reduction: warp shfl -> 2-warp smem ----
    float rs = (rsa[0] + rsa[1]) + (rsa[2] + rsa[3]);
    float ts = tsa[0] + tsa[1];
#pragma unroll
    for (int o = 16; o > 0; o >>= 1) {
        rs += __shfl_down_sync(0xffffffffu, rs, o);
        ts += __shfl_down_sync(0xffffffffu, ts, o);
    }
    const int wid = tid >> 5;
    if ((tid & 31) == 0) { red[0][wid] = rs; red[1][wid] = ts; }
    __syncthreads();

    // ---- per-block partial, then last block reduces (self-resetting counter) ----
    if (tid == 0) {
        float a = red[0][0] + red[0][1];
        float b = red[1][0] + red[1][1];
        hx_partial[blockIdx.x] = 50.0f * a + b;
        __threadfence();
        unsigned old = atomicAdd(&hx_count, 1u);
        amLast = (old == gridDim.x - 1);
    }
    __syncthreads();

    if (amLast) {
        float s = 0.0f;
        for (int i = tid; i < (int)gridDim.x; i += BPB) s += hx_partial[i];
#pragma unroll
        for (int o = 16; o > 0; o >>= 1)
            s += __shfl_down_sync(0xffffffffu, s, o);
        if ((tid & 31) == 0) red[0][tid >> 5] = s;
        __syncthreads();
        if (tid == 0) {
            out[0] = red[0][0] + red[0][1];
            hx_count = 0;            // reset for next graph replay (deterministic)
        }
    }
}

extern "C" void kernel_launch(void* const* d_in, const int* in_sizes, int n_in,
                              void* d_out, int out_size)
{
    const float* rotas  = (const float*)d_in[0];   // [10, B, 3, 3] fp32
    const float* transs = (const float*)d_in[1];   // [10, B, 3]    fp32
    float* out = (float*)d_out;                    // [1] fp32

    const int B = in_sizes[0] / (NPAIRS * 9);      // 262144
    const int ntiles = B / TILE;                   // 4096
    const int grid = ntiles < NBLOCKS ? ntiles : NBLOCKS;

    static int attr_set = 0;
    if (!attr_set) {
        cudaFuncSetAttribute(hx_accum_loss,
                             cudaFuncAttributeMaxDynamicSharedMemorySize,
                             NSTAGES * BUF_BYTES);
        attr_set = 1;
    }

    hx_accum_loss<<<grid, BPB, NSTAGES * BUF_BYTES>>>(rotas, transs, out, B);
}